// round 3
// baseline (speedup 1.0000x reference)
#include <cuda_runtime.h>
#include <math.h>

#define BB 8
#define NN 256
#define DD 48
#define VV 20
#define LL 2
#define SS 6
#define TWO_D 96
#define THREE_D 144
#define FOUR_D 192
#define ROWS (BB*NN)   // 2048

// Scratch
__device__ float g_x[ROWS * DD];
__device__ float g_p[ROWS * DD];
__device__ float g_t[ROWS * DD];
__device__ float g_A[ROWS * TWO_D];   // xi @ W1_top + b1
__device__ float g_B[ROWS * TWO_D];   // xj @ W1_bot

__device__ __forceinline__ float gelu_exact(float v) {
    return 0.5f * v * (1.0f + erff(v * 0.70710678118654752440f));
}

// ---------------------------------------------------------------------------
// Embed
// ---------------------------------------------------------------------------
__global__ void embed_kernel(const int* __restrict__ ids,
                             const float* __restrict__ embed,
                             const float* __restrict__ pos,
                             float* __restrict__ x) {
    int row = blockIdx.x;
    int n = row & (NN - 1);
    int d = threadIdx.x;
    int id = ids[row];
    x[row * DD + d] = embed[id * DD + d] + pos[n * DD + d];
}

// ---------------------------------------------------------------------------
// Precompute A[row][96] = b1 + xi @ W1[0:48,:],  B[row][96] = xj @ W1[48:96,:]
// ---------------------------------------------------------------------------
__global__ __launch_bounds__(192) void ab_kernel(const float* __restrict__ x,
                          const float* __restrict__ W1,
                          const float* __restrict__ b1,
                          float* __restrict__ A,
                          float* __restrict__ Bv) {
    __shared__ float sx[8][DD];
    int r0 = blockIdx.x * 8;
    int tid = threadIdx.x;
    for (int idx = tid; idx < 8 * DD; idx += 192)
        sx[idx / DD][idx % DD] = x[(r0 + idx / DD) * DD + (idx % DD)];
    __syncthreads();
    int col = tid % TWO_D;
    int part = tid / TWO_D;   // 0 = A, 1 = B
    const float* w = W1 + (part ? DD * TWO_D : 0) + col;
    float acc[8];
    float init = part ? 0.0f : b1[col];
    #pragma unroll
    for (int r = 0; r < 8; r++) acc[r] = init;
    #pragma unroll 4
    for (int k = 0; k < DD; k++) {
        float wv = w[k * TWO_D];
        #pragma unroll
        for (int r = 0; r < 8; r++) acc[r] = fmaf(sx[r][k], wv, acc[r]);
    }
    float* dst = part ? Bv : A;
    #pragma unroll
    for (int r = 0; r < 8; r++) dst[(r0 + r) * TWO_D + col] = acc[r];
}

// ---------------------------------------------------------------------------
// Pair module: per (b,i), tiled GEMM over j with per-ty-group online softmax.
// ---------------------------------------------------------------------------
#define PJT 32
#define PTHREADS 128
#define HP 100   // row pitch (floats): 16B aligned, bank-conflict-free

__global__ __launch_bounds__(PTHREADS) void pair_kernel(
    const float* __restrict__ A, const float* __restrict__ Bv,
    const float* __restrict__ W2, const float* __restrict__ B2,
    float* __restrict__ outp) {
    __shared__ float sW2T[DD * HP];     // [d][k]
    __shared__ float sH[PJT * HP];      // [j][k]
    __shared__ float sA[TWO_D];
    __shared__ float sb2[DD];
    __shared__ float sacc[8 * DD];
    __shared__ float slsum[8];
    __shared__ float sM[8];

    int row = blockIdx.x;
    int b = row >> 8;
    int i = row & (NN - 1);
    int tid = threadIdx.x;
    int tx = tid & 15;
    int ty = tid >> 4;
    int d0 = tx * 3;

    for (int idx = tid; idx < TWO_D * DD; idx += PTHREADS) {
        int k = idx / DD, d = idx % DD;
        sW2T[d * HP + k] = W2[idx];
    }
    if (tid < TWO_D) sA[tid] = A[row * TWO_D + tid];
    if (tid < DD) sb2[tid] = B2[tid];
    __syncthreads();

    // Per-ty-group online softmax state. wj >= 0 always, so M=0 is a safe
    // lower bound and keeps all-masked groups NaN-free.
    float M = 0.0f;
    float acc0 = 0.0f, acc1 = 0.0f, acc2 = 0.0f;
    float lsum = 0.0f;
    int numJ = i + 1;
    const float* Bbase = Bv + (b * NN) * TWO_D;

    for (int jbase = 0; jbase < numJ; jbase += PJT) {
        // Build H tile: H[j][k] = gelu(A_i[k] + B_{jbase+j}[k])
        for (int q = tid; q < PJT * (TWO_D / 4); q += PTHREADS) {
            int j = q / (TWO_D / 4);
            int kk = (q % (TWO_D / 4)) * 4;
            float4 bv = *(const float4*)(Bbase + (jbase + j) * TWO_D + kk);
            float4 hv;
            hv.x = gelu_exact(sA[kk + 0] + bv.x);
            hv.y = gelu_exact(sA[kk + 1] + bv.y);
            hv.z = gelu_exact(sA[kk + 2] + bv.z);
            hv.w = gelu_exact(sA[kk + 3] + bv.w);
            *(float4*)(sH + j * HP + kk) = hv;
        }
        __syncthreads();

        // P tile = H @ W2 + b2 ; register tile 4j x 3d per thread
        float p[4][3];
        {
            float bb0 = sb2[d0], bb1 = sb2[d0 + 1], bb2v = sb2[d0 + 2];
            #pragma unroll
            for (int jj = 0; jj < 4; jj++) { p[jj][0] = bb0; p[jj][1] = bb1; p[jj][2] = bb2v; }
        }
        #pragma unroll 4
        for (int k = 0; k < TWO_D; k += 4) {
            float4 w0 = *(const float4*)(sW2T + (d0 + 0) * HP + k);
            float4 w1 = *(const float4*)(sW2T + (d0 + 1) * HP + k);
            float4 w2 = *(const float4*)(sW2T + (d0 + 2) * HP + k);
            #pragma unroll
            for (int jj = 0; jj < 4; jj++) {
                float4 h = *(const float4*)(sH + (ty + 8 * jj) * HP + k);
                p[jj][0] = fmaf(h.x, w0.x, p[jj][0]); p[jj][0] = fmaf(h.y, w0.y, p[jj][0]);
                p[jj][0] = fmaf(h.z, w0.z, p[jj][0]); p[jj][0] = fmaf(h.w, w0.w, p[jj][0]);
                p[jj][1] = fmaf(h.x, w1.x, p[jj][1]); p[jj][1] = fmaf(h.y, w1.y, p[jj][1]);
                p[jj][1] = fmaf(h.z, w1.z, p[jj][1]); p[jj][1] = fmaf(h.w, w1.w, p[jj][1]);
                p[jj][2] = fmaf(h.x, w2.x, p[jj][2]); p[jj][2] = fmaf(h.y, w2.y, p[jj][2]);
                p[jj][2] = fmaf(h.z, w2.z, p[jj][2]); p[jj][2] = fmaf(h.w, w2.w, p[jj][2]);
            }
        }

        // Pair-feature norms: reduce across the 16 tx lanes
        float wj[4];
        #pragma unroll
        for (int jj = 0; jj < 4; jj++) {
            float sq = p[jj][0] * p[jj][0] + p[jj][1] * p[jj][1] + p[jj][2] * p[jj][2];
            #pragma unroll
            for (int o = 1; o < 16; o <<= 1) sq += __shfl_xor_sync(0xFFFFFFFFu, sq, o);
            int j = jbase + ty + 8 * jj;
            wj[jj] = (j <= i) ? sqrtf(sq) : -INFINITY;
        }

        // Per-ty-group online softmax update (no cross-group sync needed)
        float tmax = fmaxf(fmaxf(wj[0], wj[1]), fmaxf(wj[2], wj[3]));
        float newM = fmaxf(M, tmax);
        float sc = __expf(M - newM);
        acc0 *= sc; acc1 *= sc; acc2 *= sc; lsum *= sc;
        #pragma unroll
        for (int jj = 0; jj < 4; jj++) {
            float e = __expf(wj[jj] - newM);   // exactly 0 for masked j
            acc0 = fmaf(e, p[jj][0], acc0);
            acc1 = fmaf(e, p[jj][1], acc1);
            acc2 = fmaf(e, p[jj][2], acc2);
            lsum += e;
        }
        M = newM;
        __syncthreads();   // protect sH before next tile overwrites
    }

    sacc[ty * DD + d0 + 0] = acc0;
    sacc[ty * DD + d0 + 1] = acc1;
    sacc[ty * DD + d0 + 2] = acc2;
    if (tx == 0) { slsum[ty] = lsum; sM[ty] = M; }
    __syncthreads();

    if (tid < DD) {
        float Mstar = sM[0];
        #pragma unroll
        for (int w = 1; w < 8; w++) Mstar = fmaxf(Mstar, sM[w]);
        float a = 0.0f, L = 0.0f;
        #pragma unroll
        for (int w = 0; w < 8; w++) {
            float s = __expf(sM[w] - Mstar);
            a = fmaf(s, sacc[w * DD + tid], a);
            L = fmaf(s, slsum[w], L);
        }
        outp[row * DD + tid] = a / L;
    }
}

// ---------------------------------------------------------------------------
// Triple module: 4 rows x 6 s = 24 items per block; each W1/W2 load feeds
// 24/12 FMAs (ILP + L2 traffic / 4).
// ---------------------------------------------------------------------------
#define TR 4
#define TITEMS (TR*SS)   // 24

__global__ __launch_bounds__(TWO_D) void triple_kernel(const float* __restrict__ x,
                              const int* __restrict__ ji,
                              const int* __restrict__ ki,
                              const float* __restrict__ W1,
                              const float* __restrict__ B1,
                              const float* __restrict__ W2,
                              const float* __restrict__ B2,
                              float* __restrict__ outt) {
    __shared__ float v[TITEMS][THREE_D];
    __shared__ float hh[TITEMS][TWO_D];
    __shared__ int sidx[TITEMS][2];
    int r0 = blockIdx.x * TR;
    int b = r0 >> 8;           // TR divides 256, so all rows share b
    int tid = threadIdx.x;     // 96

    if (tid < TITEMS * 2) {
        int q = tid >> 1;            // item = r*SS + s
        int r = q / SS, s = q % SS;
        int row = r0 + r;
        sidx[q][tid & 1] = (tid & 1) ? ki[row * SS + s] : ji[row * SS + s];
    }
    __syncthreads();

    // Gather v[item] = concat(xi, xj, xk), float4 loads
    for (int q = tid; q < TITEMS * 36; q += TWO_D) {
        int item = q / 36;
        int rem = q % 36;
        int seg = rem / 12;          // 0=xi, 1=xj, 2=xk
        int f4 = rem % 12;
        int srcrow = (seg == 0) ? (r0 + item / SS) : (b * NN + sidx[item][seg - 1]);
        float4 val = *(const float4*)(x + srcrow * DD + f4 * 4);
        *(float4*)(&v[item][seg * DD + f4 * 4]) = val;
    }
    __syncthreads();

    // Layer 1: h[item] over all 24 items, col = tid
    {
        float h[TITEMS];
        float bb = B1[tid];
        #pragma unroll
        for (int q = 0; q < TITEMS; q++) h[q] = bb;
        #pragma unroll 2
        for (int k = 0; k < THREE_D; k++) {
            float w = W1[k * TWO_D + tid];
            #pragma unroll
            for (int q = 0; q < TITEMS; q++) h[q] = fmaf(v[q][k], w, h[q]);
        }
        #pragma unroll
        for (int q = 0; q < TITEMS; q++) hh[q][tid] = gelu_exact(h[q]);
    }
    __syncthreads();

    // Layer 2: col = tid%48, group g = tid/48 handles items [12g, 12g+12)
    {
        int col = tid % DD;
        int g = tid / DD;            // 0 or 1
        float p[12];
        float bb = B2[col];
        #pragma unroll
        for (int q = 0; q < 12; q++) p[q] = bb;
        #pragma unroll 2
        for (int k = 0; k < TWO_D; k++) {
            float w = W2[k * DD + col];
            #pragma unroll
            for (int q = 0; q < 12; q++) p[q] = fmaf(hh[g * 12 + q][k], w, p[q]);
        }
        // items g*12..g*12+11 cover rows 2g and 2g+1 (6 s each)
        #pragma unroll
        for (int rr = 0; rr < 2; rr++) {
            int r = 2 * g + rr;
            float acc = 0.0f;
            #pragma unroll
            for (int s = 0; s < SS; s++) acc += p[rr * SS + s];
            outt[(r0 + r) * DD + col] = acc * (1.0f / 6.0f);
        }
    }
}

// ---------------------------------------------------------------------------
// Fused gate/mix/LN1 + FFN/LN2. 192 threads / block.
// ---------------------------------------------------------------------------
__global__ __launch_bounds__(FOUR_D) void mixffn_kernel(float* __restrict__ x,
                              const float* __restrict__ p,
                              const float* __restrict__ t,
                              const float* __restrict__ Gw,
                              const float* __restrict__ Gb,
                              const float* __restrict__ n1g,
                              const float* __restrict__ n1b,
                              const float* __restrict__ W1,
                              const float* __restrict__ B1,
                              const float* __restrict__ W2,
                              const float* __restrict__ B2,
                              const float* __restrict__ n2g,
                              const float* __restrict__ n2b) {
    __shared__ float sp[DD], st[DD], sx[DD], sy[DD], sg[2 * DD], sh2[FOUR_D];
    int row = blockIdx.x;
    int tid = threadIdx.x;
    if (tid < DD) {
        sp[tid] = p[row * DD + tid];
        st[tid] = t[row * DD + tid];
        sx[tid] = x[row * DD + tid];
    }
    __syncthreads();
    if (tid < 2 * DD) {
        int d = tid % DD;
        int part = tid / DD;
        const float* src = part ? st : sp;
        const float* gw = Gw + part * DD * DD;
        float s = 0.0f;
        #pragma unroll 8
        for (int c = 0; c < DD; c++) s = fmaf(src[c], gw[c * DD + d], s);
        sg[tid] = s;
    }
    __syncthreads();
    if (tid < DD) {
        float gsum = sg[tid] + sg[DD + tid] + Gb[tid];
        float g = 1.0f / (1.0f + __expf(-gsum));
        sy[tid] = sx[tid] + g * sp[tid] + (1.0f - g) * st[tid];
    }
    __syncthreads();
    if (tid < DD) {
        float mu = 0.0f;
        #pragma unroll 8
        for (int c = 0; c < DD; c++) mu += sy[c];
        mu *= (1.0f / DD);
        float var = 0.0f;
        #pragma unroll 8
        for (int c = 0; c < DD; c++) { float d = sy[c] - mu; var = fmaf(d, d, var); }
        var *= (1.0f / DD);
        sp[tid] = (sy[tid] - mu) * rsqrtf(var + 1e-5f) * n1g[tid] + n1b[tid];
    }
    __syncthreads();
    {
        float h = B1[tid];
        #pragma unroll 8
        for (int c = 0; c < DD; c++) h = fmaf(sp[c], W1[c * FOUR_D + tid], h);
        sh2[tid] = gelu_exact(h);
    }
    __syncthreads();
    if (tid < DD) {
        float o = B2[tid];
        #pragma unroll 8
        for (int k = 0; k < FOUR_D; k++) o = fmaf(sh2[k], W2[k * DD + tid], o);
        sy[tid] = sp[tid] + o;
    }
    __syncthreads();
    if (tid < DD) {
        float mu = 0.0f;
        #pragma unroll 8
        for (int c = 0; c < DD; c++) mu += sy[c];
        mu *= (1.0f / DD);
        float var = 0.0f;
        #pragma unroll 8
        for (int c = 0; c < DD; c++) { float d = sy[c] - mu; var = fmaf(d, d, var); }
        var *= (1.0f / DD);
        x[row * DD + tid] = (sy[tid] - mu) * rsqrtf(var + 1e-5f) * n2g[tid] + n2b[tid];
    }
}

// ---------------------------------------------------------------------------
// Head
// ---------------------------------------------------------------------------
__global__ void head_kernel(const float* __restrict__ x,
                            const float* __restrict__ Hw,
                            const float* __restrict__ Hb,
                            float* __restrict__ out) {
    __shared__ float sx[DD];
    int row = blockIdx.x;
    int tid = threadIdx.x;
    sx[tid] = x[row * DD + tid];
    if (tid < 16) sx[tid + 32] = x[row * DD + tid + 32];
    __syncwarp();
    if (tid < VV) {
        float o = Hb[tid];
        #pragma unroll 8
        for (int d = 0; d < DD; d++) o = fmaf(sx[d], Hw[d * VV + tid], o);
        out[row * VV + tid] = o;
    }
}

// ---------------------------------------------------------------------------
// Launch
// ---------------------------------------------------------------------------
extern "C" void kernel_launch(void* const* d_in, const int* in_sizes, int n_in,
                              void* d_out, int out_size) {
    const int*   ids     = (const int*)d_in[0];
    const int*   ji      = (const int*)d_in[1];
    const int*   ki      = (const int*)d_in[2];
    const float* embed   = (const float*)d_in[3];
    const float* pos     = (const float*)d_in[4];
    const float* pair_w1 = (const float*)d_in[5];
    const float* pair_b1 = (const float*)d_in[6];
    const float* pair_w2 = (const float*)d_in[7];
    const float* pair_b2 = (const float*)d_in[8];
    const float* tri_w1  = (const float*)d_in[9];
    const float* tri_b1  = (const float*)d_in[10];
    const float* tri_w2  = (const float*)d_in[11];
    const float* tri_b2  = (const float*)d_in[12];
    const float* gate_w  = (const float*)d_in[13];
    const float* gate_b  = (const float*)d_in[14];
    const float* n1_g    = (const float*)d_in[15];
    const float* n1_b    = (const float*)d_in[16];
    const float* ffn_w1  = (const float*)d_in[17];
    const float* ffn_b1  = (const float*)d_in[18];
    const float* ffn_w2  = (const float*)d_in[19];
    const float* ffn_b2  = (const float*)d_in[20];
    const float* n2_g    = (const float*)d_in[21];
    const float* n2_b    = (const float*)d_in[22];
    const float* head_w  = (const float*)d_in[23];
    const float* head_b  = (const float*)d_in[24];
    float* out = (float*)d_out;

    float* x; cudaGetSymbolAddress((void**)&x, g_x);
    float* p; cudaGetSymbolAddress((void**)&p, g_p);
    float* t; cudaGetSymbolAddress((void**)&t, g_t);
    float* Aa; cudaGetSymbolAddress((void**)&Aa, g_A);
    float* Bb; cudaGetSymbolAddress((void**)&Bb, g_B);

    embed_kernel<<<ROWS, DD>>>(ids, embed, pos, x);

    for (int l = 0; l < LL; l++) {
        ab_kernel<<<ROWS / 8, 192>>>(x, pair_w1 + l * TWO_D * TWO_D,
                                     pair_b1 + l * TWO_D, Aa, Bb);
        pair_kernel<<<ROWS, PTHREADS>>>(Aa, Bb,
            pair_w2 + l * TWO_D * DD, pair_b2 + l * DD, p);
        triple_kernel<<<ROWS / TR, TWO_D>>>(
            x, ji + l * ROWS * SS, ki + l * ROWS * SS,
            tri_w1 + l * THREE_D * TWO_D, tri_b1 + l * TWO_D,
            tri_w2 + l * TWO_D * DD,      tri_b2 + l * DD, t);
        mixffn_kernel<<<ROWS, FOUR_D>>>(
            x, p, t,
            gate_w + l * TWO_D * DD, gate_b + l * DD,
            n1_g + l * DD, n1_b + l * DD,
            ffn_w1 + l * DD * FOUR_D, ffn_b1 + l * FOUR_D,
            ffn_w2 + l * FOUR_D * DD, ffn_b2 + l * DD,
            n2_g + l * DD, n2_b + l * DD);
    }

    head_kernel<<<ROWS, 32>>>(x, head_w, head_b, out);
}

// round 4
// speedup vs baseline: 1.0471x; 1.0471x over previous
#include <cuda_runtime.h>
#include <math.h>

#define BB 8
#define NN 256
#define DD 48
#define VV 20
#define LL 2
#define SS 6
#define TWO_D 96
#define THREE_D 144
#define FOUR_D 192
#define ROWS (BB*NN)   // 2048

// Scratch
__device__ float g_x[ROWS * DD];
__device__ float g_p[ROWS * DD];
__device__ float g_t[ROWS * DD];
__device__ float g_A[ROWS * TWO_D];   // xi @ W1_top + b1
__device__ float g_B[ROWS * TWO_D];   // xj @ W1_bot

__device__ __forceinline__ float gelu_exact(float v) {
    return 0.5f * v * (1.0f + erff(v * 0.70710678118654752440f));
}

// ---------------------------------------------------------------------------
// Embed
// ---------------------------------------------------------------------------
__global__ void embed_kernel(const int* __restrict__ ids,
                             const float* __restrict__ embed,
                             const float* __restrict__ pos,
                             float* __restrict__ x) {
    int row = blockIdx.x;
    int n = row & (NN - 1);
    int d = threadIdx.x;
    int id = ids[row];
    x[row * DD + d] = embed[id * DD + d] + pos[n * DD + d];
}

// ---------------------------------------------------------------------------
// Precompute A[row][96] = b1 + xi @ W1[0:48,:],  B[row][96] = xj @ W1[48:96,:]
// ---------------------------------------------------------------------------
__global__ __launch_bounds__(192) void ab_kernel(const float* __restrict__ x,
                          const float* __restrict__ W1,
                          const float* __restrict__ b1,
                          float* __restrict__ A,
                          float* __restrict__ Bv) {
    __shared__ float sx[8][DD];
    int r0 = blockIdx.x * 8;
    int tid = threadIdx.x;
    for (int idx = tid; idx < 8 * DD; idx += 192)
        sx[idx / DD][idx % DD] = x[(r0 + idx / DD) * DD + (idx % DD)];
    __syncthreads();
    int col = tid % TWO_D;
    int part = tid / TWO_D;   // 0 = A, 1 = B
    const float* w = W1 + (part ? DD * TWO_D : 0) + col;
    float acc[8];
    float init = part ? 0.0f : b1[col];
    #pragma unroll
    for (int r = 0; r < 8; r++) acc[r] = init;
    #pragma unroll 4
    for (int k = 0; k < DD; k++) {
        float wv = w[k * TWO_D];
        #pragma unroll
        for (int r = 0; r < 8; r++) acc[r] = fmaf(sx[r][k], wv, acc[r]);
    }
    float* dst = part ? Bv : A;
    #pragma unroll
    for (int r = 0; r < 8; r++) dst[(r0 + r) * TWO_D + col] = acc[r];
}

// ---------------------------------------------------------------------------
// Pair module: per (b,i), tiled GEMM over j with per-group online softmax.
// Thread tile 4j x 6d; tx in [0,8) owns d = {tx, tx+8, ..., tx+40};
// ty in [0,16) owns j = ty + 16*jj, jj<4. PJT=64.
// ---------------------------------------------------------------------------
#define PJT 64
#define PTHREADS 128
#define HP 100   // row pitch (floats): 16B aligned; w rows hit banks 4*tx (clean)

__global__ __launch_bounds__(PTHREADS) void pair_kernel(
    const float* __restrict__ A, const float* __restrict__ Bv,
    const float* __restrict__ W2, const float* __restrict__ B2,
    float* __restrict__ outp) {
    __shared__ float sW2T[DD * HP];     // [d][k]  (4800 f)
    __shared__ float sH[PJT * HP];      // [j][k]  (6400 f)
    __shared__ float sA[TWO_D];
    __shared__ float sb2[DD];
    __shared__ float sacc[16 * DD];     // per ty-group accumulators
    __shared__ float slsum[16];
    __shared__ float sM[16];

    int row = blockIdx.x;
    int b = row >> 8;
    int i = row & (NN - 1);
    int tid = threadIdx.x;
    int tx = tid & 7;        // d-group
    int ty = tid >> 3;       // j-group, [0,16)

    for (int idx = tid; idx < TWO_D * DD; idx += PTHREADS) {
        int k = idx / DD, d = idx % DD;
        sW2T[d * HP + k] = W2[idx];
    }
    if (tid < TWO_D) sA[tid] = A[row * TWO_D + tid];
    if (tid < DD) sb2[tid] = B2[tid];
    __syncthreads();

    // Per-ty-group online softmax state (wj >= 0, so M=0 is a safe floor).
    float M = 0.0f;
    float acc[6];
    #pragma unroll
    for (int m = 0; m < 6; m++) acc[m] = 0.0f;
    float lsum = 0.0f;
    int numJ = i + 1;
    const float* Bbase = Bv + (b * NN) * TWO_D;

    float bia[6];
    #pragma unroll
    for (int m = 0; m < 6; m++) bia[m] = sb2[tx + 8 * m];

    for (int jbase = 0; jbase < numJ; jbase += PJT) {
        // Build H tile: H[j][k] = gelu(A_i[k] + B_{jbase+j}[k])
        for (int q = tid; q < PJT * (TWO_D / 4); q += PTHREADS) {
            int j = q / (TWO_D / 4);
            int kk = (q % (TWO_D / 4)) * 4;
            float4 bv = *(const float4*)(Bbase + (jbase + j) * TWO_D + kk);
            float4 hv;
            hv.x = gelu_exact(sA[kk + 0] + bv.x);
            hv.y = gelu_exact(sA[kk + 1] + bv.y);
            hv.z = gelu_exact(sA[kk + 2] + bv.z);
            hv.w = gelu_exact(sA[kk + 3] + bv.w);
            *(float4*)(sH + j * HP + kk) = hv;
        }
        __syncthreads();

        // P tile: thread tile 4j x 6d
        float p[4][6];
        #pragma unroll
        for (int jj = 0; jj < 4; jj++)
            #pragma unroll
            for (int m = 0; m < 6; m++) p[jj][m] = bia[m];

        #pragma unroll 4
        for (int k = 0; k < TWO_D; k += 4) {
            float4 w[6];
            #pragma unroll
            for (int m = 0; m < 6; m++)
                w[m] = *(const float4*)(sW2T + (tx + 8 * m) * HP + k);
            #pragma unroll
            for (int jj = 0; jj < 4; jj++) {
                float4 h = *(const float4*)(sH + (ty + 16 * jj) * HP + k);
                #pragma unroll
                for (int m = 0; m < 6; m++) {
                    p[jj][m] = fmaf(h.x, w[m].x, p[jj][m]);
                    p[jj][m] = fmaf(h.y, w[m].y, p[jj][m]);
                    p[jj][m] = fmaf(h.z, w[m].z, p[jj][m]);
                    p[jj][m] = fmaf(h.w, w[m].w, p[jj][m]);
                }
            }
        }

        // Pair-feature norms: reduce across the 8 tx lanes of this ty-group
        float wj[4];
        #pragma unroll
        for (int jj = 0; jj < 4; jj++) {
            float sq = 0.0f;
            #pragma unroll
            for (int m = 0; m < 6; m++) sq = fmaf(p[jj][m], p[jj][m], sq);
            sq += __shfl_xor_sync(0xFFFFFFFFu, sq, 1);
            sq += __shfl_xor_sync(0xFFFFFFFFu, sq, 2);
            sq += __shfl_xor_sync(0xFFFFFFFFu, sq, 4);
            int j = jbase + ty + 16 * jj;
            wj[jj] = (j <= i) ? sqrtf(sq) : -INFINITY;
        }

        // Per-group online softmax update
        float tmax = fmaxf(fmaxf(wj[0], wj[1]), fmaxf(wj[2], wj[3]));
        float newM = fmaxf(M, tmax);
        float sc = __expf(M - newM);
        #pragma unroll
        for (int m = 0; m < 6; m++) acc[m] *= sc;
        lsum *= sc;
        #pragma unroll
        for (int jj = 0; jj < 4; jj++) {
            float e = __expf(wj[jj] - newM);   // exactly 0 for masked j
            #pragma unroll
            for (int m = 0; m < 6; m++) acc[m] = fmaf(e, p[jj][m], acc[m]);
            lsum += e;
        }
        M = newM;
        __syncthreads();   // protect sH before next tile overwrites
    }

    #pragma unroll
    for (int m = 0; m < 6; m++) sacc[ty * DD + tx + 8 * m] = acc[m];
    if (tx == 0) { slsum[ty] = lsum; sM[ty] = M; }
    __syncthreads();

    if (tid < DD) {
        float Mstar = sM[0];
        #pragma unroll
        for (int w = 1; w < 16; w++) Mstar = fmaxf(Mstar, sM[w]);
        float a = 0.0f, L = 0.0f;
        #pragma unroll
        for (int w = 0; w < 16; w++) {
            float s = __expf(sM[w] - Mstar);
            a = fmaf(s, sacc[w * DD + tid], a);
            L = fmaf(s, slsum[w], L);
        }
        outp[row * DD + tid] = a / L;
    }
}

// ---------------------------------------------------------------------------
// Triple module: one row per block (grid 2048, 96 threads), 6-item batch,
// float4 broadcast LDS on v/hh + 4-wide LDG prefetch of W.
// ---------------------------------------------------------------------------
__global__ __launch_bounds__(TWO_D) void triple_kernel(const float* __restrict__ x,
                              const int* __restrict__ ji,
                              const int* __restrict__ ki,
                              const float* __restrict__ W1,
                              const float* __restrict__ B1,
                              const float* __restrict__ W2,
                              const float* __restrict__ B2,
                              float* __restrict__ outt) {
    __shared__ __align__(16) float v[SS][THREE_D];
    __shared__ __align__(16) float hh[SS][TWO_D];
    __shared__ float sp2[2][DD];
    __shared__ int sidx[SS][2];
    int row = blockIdx.x;
    int b = row >> 8;
    int tid = threadIdx.x;     // 96

    if (tid < SS * 2) {
        int s = tid >> 1;
        sidx[s][tid & 1] = (tid & 1) ? ki[row * SS + s] : ji[row * SS + s];
    }
    __syncthreads();

    // Gather v[s] = concat(xi, xj, xk), float4 loads (6*36 = 216 float4)
    for (int q = tid; q < SS * 36; q += TWO_D) {
        int s = q / 36;
        int rem = q % 36;
        int seg = rem / 12;          // 0=xi, 1=xj, 2=xk
        int f4 = rem % 12;
        int srcrow = (seg == 0) ? row : (b * NN + sidx[s][seg - 1]);
        float4 val = *(const float4*)(x + srcrow * DD + f4 * 4);
        *(float4*)(&v[s][seg * DD + f4 * 4]) = val;
    }
    __syncthreads();

    // Layer 1: col = tid, all 6 items. 4-wide k chunks.
    {
        float h[SS];
        float bb = B1[tid];
        #pragma unroll
        for (int s = 0; s < SS; s++) h[s] = bb;
        const float* w1c = W1 + tid;
        #pragma unroll 3
        for (int k = 0; k < THREE_D; k += 4) {
            float w0 = w1c[(k + 0) * TWO_D];
            float w1 = w1c[(k + 1) * TWO_D];
            float w2 = w1c[(k + 2) * TWO_D];
            float w3 = w1c[(k + 3) * TWO_D];
            #pragma unroll
            for (int s = 0; s < SS; s++) {
                float4 vv = *(const float4*)(&v[s][k]);
                h[s] = fmaf(vv.x, w0, h[s]);
                h[s] = fmaf(vv.y, w1, h[s]);
                h[s] = fmaf(vv.z, w2, h[s]);
                h[s] = fmaf(vv.w, w3, h[s]);
            }
        }
        #pragma unroll
        for (int s = 0; s < SS; s++) hh[s][tid] = gelu_exact(h[s]);
    }
    __syncthreads();

    // Layer 2: col = tid%48, g = tid/48 handles items 3g..3g+2
    {
        int col = tid % DD;
        int g = tid / DD;            // 0 or 1
        float p[3];
        float bb = B2[col];
        #pragma unroll
        for (int q = 0; q < 3; q++) p[q] = bb;
        const float* w2c = W2 + col;
        #pragma unroll 3
        for (int k = 0; k < TWO_D; k += 4) {
            float w0 = w2c[(k + 0) * DD];
            float w1 = w2c[(k + 1) * DD];
            float w2 = w2c[(k + 2) * DD];
            float w3 = w2c[(k + 3) * DD];
            #pragma unroll
            for (int q = 0; q < 3; q++) {
                float4 hv = *(const float4*)(&hh[g * 3 + q][k]);
                p[q] = fmaf(hv.x, w0, p[q]);
                p[q] = fmaf(hv.y, w1, p[q]);
                p[q] = fmaf(hv.z, w2, p[q]);
                p[q] = fmaf(hv.w, w3, p[q]);
            }
        }
        sp2[g][col] = p[0] + p[1] + p[2];
    }
    __syncthreads();
    if (tid < DD)
        outt[row * DD + tid] = (sp2[0][tid] + sp2[1][tid]) * (1.0f / 6.0f);
}

// ---------------------------------------------------------------------------
// Fused gate/mix/LN1 + FFN/LN2. 192 threads / block.
// ---------------------------------------------------------------------------
__global__ __launch_bounds__(FOUR_D) void mixffn_kernel(float* __restrict__ x,
                              const float* __restrict__ p,
                              const float* __restrict__ t,
                              const float* __restrict__ Gw,
                              const float* __restrict__ Gb,
                              const float* __restrict__ n1g,
                              const float* __restrict__ n1b,
                              const float* __restrict__ W1,
                              const float* __restrict__ B1,
                              const float* __restrict__ W2,
                              const float* __restrict__ B2,
                              const float* __restrict__ n2g,
                              const float* __restrict__ n2b) {
    __shared__ float sp[DD], st[DD], sx[DD], sy[DD], sg[2 * DD], sh2[FOUR_D];
    int row = blockIdx.x;
    int tid = threadIdx.x;
    if (tid < DD) {
        sp[tid] = p[row * DD + tid];
        st[tid] = t[row * DD + tid];
        sx[tid] = x[row * DD + tid];
    }
    __syncthreads();
    if (tid < 2 * DD) {
        int d = tid % DD;
        int part = tid / DD;
        const float* src = part ? st : sp;
        const float* gw = Gw + part * DD * DD;
        float s = 0.0f;
        #pragma unroll 8
        for (int c = 0; c < DD; c++) s = fmaf(src[c], gw[c * DD + d], s);
        sg[tid] = s;
    }
    __syncthreads();
    if (tid < DD) {
        float gsum = sg[tid] + sg[DD + tid] + Gb[tid];
        float g = 1.0f / (1.0f + __expf(-gsum));
        sy[tid] = sx[tid] + g * sp[tid] + (1.0f - g) * st[tid];
    }
    __syncthreads();
    if (tid < DD) {
        float mu = 0.0f;
        #pragma unroll 8
        for (int c = 0; c < DD; c++) mu += sy[c];
        mu *= (1.0f / DD);
        float var = 0.0f;
        #pragma unroll 8
        for (int c = 0; c < DD; c++) { float d = sy[c] - mu; var = fmaf(d, d, var); }
        var *= (1.0f / DD);
        sp[tid] = (sy[tid] - mu) * rsqrtf(var + 1e-5f) * n1g[tid] + n1b[tid];
    }
    __syncthreads();
    {
        float h = B1[tid];
        #pragma unroll 8
        for (int c = 0; c < DD; c++) h = fmaf(sp[c], W1[c * FOUR_D + tid], h);
        sh2[tid] = gelu_exact(h);
    }
    __syncthreads();
    if (tid < DD) {
        float o = B2[tid];
        #pragma unroll 8
        for (int k = 0; k < FOUR_D; k++) o = fmaf(sh2[k], W2[k * DD + tid], o);
        sy[tid] = sp[tid] + o;
    }
    __syncthreads();
    if (tid < DD) {
        float mu = 0.0f;
        #pragma unroll 8
        for (int c = 0; c < DD; c++) mu += sy[c];
        mu *= (1.0f / DD);
        float var = 0.0f;
        #pragma unroll 8
        for (int c = 0; c < DD; c++) { float d = sy[c] - mu; var = fmaf(d, d, var); }
        var *= (1.0f / DD);
        x[row * DD + tid] = (sy[tid] - mu) * rsqrtf(var + 1e-5f) * n2g[tid] + n2b[tid];
    }
}

// ---------------------------------------------------------------------------
// Head
// ---------------------------------------------------------------------------
__global__ void head_kernel(const float* __restrict__ x,
                            const float* __restrict__ Hw,
                            const float* __restrict__ Hb,
                            float* __restrict__ out) {
    __shared__ float sx[DD];
    int row = blockIdx.x;
    int tid = threadIdx.x;
    sx[tid] = x[row * DD + tid];
    if (tid < 16) sx[tid + 32] = x[row * DD + tid + 32];
    __syncwarp();
    if (tid < VV) {
        float o = Hb[tid];
        #pragma unroll 8
        for (int d = 0; d < DD; d++) o = fmaf(sx[d], Hw[d * VV + tid], o);
        out[row * VV + tid] = o;
    }
}

// ---------------------------------------------------------------------------
// Launch
// ---------------------------------------------------------------------------
extern "C" void kernel_launch(void* const* d_in, const int* in_sizes, int n_in,
                              void* d_out, int out_size) {
    const int*   ids     = (const int*)d_in[0];
    const int*   ji      = (const int*)d_in[1];
    const int*   ki      = (const int*)d_in[2];
    const float* embed   = (const float*)d_in[3];
    const float* pos     = (const float*)d_in[4];
    const float* pair_w1 = (const float*)d_in[5];
    const float* pair_b1 = (const float*)d_in[6];
    const float* pair_w2 = (const float*)d_in[7];
    const float* pair_b2 = (const float*)d_in[8];
    const float* tri_w1  = (const float*)d_in[9];
    const float* tri_b1  = (const float*)d_in[10];
    const float* tri_w2  = (const float*)d_in[11];
    const float* tri_b2  = (const float*)d_in[12];
    const float* gate_w  = (const float*)d_in[13];
    const float* gate_b  = (const float*)d_in[14];
    const float* n1_g    = (const float*)d_in[15];
    const float* n1_b    = (const float*)d_in[16];
    const float* ffn_w1  = (const float*)d_in[17];
    const float* ffn_b1  = (const float*)d_in[18];
    const float* ffn_w2  = (const float*)d_in[19];
    const float* ffn_b2  = (const float*)d_in[20];
    const float* n2_g    = (const float*)d_in[21];
    const float* n2_b    = (const float*)d_in[22];
    const float* head_w  = (const float*)d_in[23];
    const float* head_b  = (const float*)d_in[24];
    float* out = (float*)d_out;

    float* x; cudaGetSymbolAddress((void**)&x, g_x);
    float* p; cudaGetSymbolAddress((void**)&p, g_p);
    float* t; cudaGetSymbolAddress((void**)&t, g_t);
    float* Aa; cudaGetSymbolAddress((void**)&Aa, g_A);
    float* Bb; cudaGetSymbolAddress((void**)&Bb, g_B);

    embed_kernel<<<ROWS, DD>>>(ids, embed, pos, x);

    for (int l = 0; l < LL; l++) {
        ab_kernel<<<ROWS / 8, 192>>>(x, pair_w1 + l * TWO_D * TWO_D,
                                     pair_b1 + l * TWO_D, Aa, Bb);
        pair_kernel<<<ROWS, PTHREADS>>>(Aa, Bb,
            pair_w2 + l * TWO_D * DD, pair_b2 + l * DD, p);
        triple_kernel<<<ROWS, TWO_D>>>(
            x, ji + l * ROWS * SS, ki + l * ROWS * SS,
            tri_w1 + l * THREE_D * TWO_D, tri_b1 + l * TWO_D,
            tri_w2 + l * TWO_D * DD,      tri_b2 + l * DD, t);
        mixffn_kernel<<<ROWS, FOUR_D>>>(
            x, p, t,
            gate_w + l * TWO_D * DD, gate_b + l * DD,
            n1_g + l * DD, n1_b + l * DD,
            ffn_w1 + l * DD * FOUR_D, ffn_b1 + l * FOUR_D,
            ffn_w2 + l * FOUR_D * DD, ffn_b2 + l * DD,
            n2_g + l * DD, n2_b + l * DD);
    }

    head_kernel<<<ROWS, 32>>>(x, head_w, head_b, out);
}

// round 5
// speedup vs baseline: 1.0698x; 1.0217x over previous
#include <cuda_runtime.h>
#include <math.h>

#define BB 8
#define NN 256
#define DD 48
#define VV 20
#define LL 2
#define SS 6
#define TWO_D 96
#define THREE_D 144
#define FOUR_D 192
#define ROWS (BB*NN)   // 2048

// Scratch
__device__ float g_x[ROWS * DD];
__device__ float g_p[ROWS * DD];
__device__ float g_t[ROWS * DD];
__device__ float g_A[ROWS * TWO_D];   // xi @ W1_top + b1
__device__ float g_B[ROWS * TWO_D];   // xj @ W1_bot

__device__ __forceinline__ float gelu_exact(float v) {
    return 0.5f * v * (1.0f + erff(v * 0.70710678118654752440f));
}

// Packed dual-fp32 FMA (Blackwell f32x2). d = a*b + c elementwise on 2 floats.
__device__ __forceinline__ unsigned long long fma2(unsigned long long a,
                                                   unsigned long long b,
                                                   unsigned long long c) {
    unsigned long long d;
    asm("fma.rn.f32x2 %0, %1, %2, %3;" : "=l"(d) : "l"(a), "l"(b), "l"(c));
    return d;
}

union F2U { unsigned long long u; float2 f; };

// ---------------------------------------------------------------------------
// Embed
// ---------------------------------------------------------------------------
__global__ void embed_kernel(const int* __restrict__ ids,
                             const float* __restrict__ embed,
                             const float* __restrict__ pos,
                             float* __restrict__ x) {
    int row = blockIdx.x;
    int n = row & (NN - 1);
    int d = threadIdx.x;
    int id = ids[row];
    x[row * DD + d] = embed[id * DD + d] + pos[n * DD + d];
}

// ---------------------------------------------------------------------------
// Precompute A[row][96] = b1 + xi @ W1[0:48,:],  B[row][96] = xj @ W1[48:96,:]
// ---------------------------------------------------------------------------
__global__ __launch_bounds__(192) void ab_kernel(const float* __restrict__ x,
                          const float* __restrict__ W1,
                          const float* __restrict__ b1,
                          float* __restrict__ A,
                          float* __restrict__ Bv) {
    __shared__ float sx[8][DD];
    int r0 = blockIdx.x * 8;
    int tid = threadIdx.x;
    for (int idx = tid; idx < 8 * DD; idx += 192)
        sx[idx / DD][idx % DD] = x[(r0 + idx / DD) * DD + (idx % DD)];
    __syncthreads();
    int col = tid % TWO_D;
    int part = tid / TWO_D;   // 0 = A, 1 = B
    const float* w = W1 + (part ? DD * TWO_D : 0) + col;
    float acc[8];
    float init = part ? 0.0f : b1[col];
    #pragma unroll
    for (int r = 0; r < 8; r++) acc[r] = init;
    #pragma unroll 4
    for (int k = 0; k < DD; k++) {
        float wv = w[k * TWO_D];
        #pragma unroll
        for (int r = 0; r < 8; r++) acc[r] = fmaf(sx[r][k], wv, acc[r]);
    }
    float* dst = part ? Bv : A;
    #pragma unroll
    for (int r = 0; r < 8; r++) dst[(r0 + r) * TWO_D + col] = acc[r];
}

// ---------------------------------------------------------------------------
// Pair module: per (b,i), tiled GEMM over j (f32x2 packed FMA) with
// per-group online softmax. Thread tile 4j x 6d; tx in [0,8) owns
// d = {tx, tx+8, ..., tx+40}; ty in [0,16) owns j = ty + 16*jj. PJT=64.
// ---------------------------------------------------------------------------
#define PJT 64
#define PTHREADS 128
#define HP 100   // row pitch (floats): 16B aligned; conflict-free

__global__ __launch_bounds__(PTHREADS) void pair_kernel(
    const float* __restrict__ A, const float* __restrict__ Bv,
    const float* __restrict__ W2, const float* __restrict__ B2,
    float* __restrict__ outp) {
    __shared__ __align__(16) float sW2T[DD * HP];     // [d][k]
    __shared__ __align__(16) float sH[PJT * HP];      // [j][k]
    __shared__ float sA[TWO_D];
    __shared__ float sb2[DD];
    __shared__ float sacc[16 * DD];
    __shared__ float slsum[16];
    __shared__ float sM[16];

    int row = blockIdx.x;
    int b = row >> 8;
    int i = row & (NN - 1);
    int tid = threadIdx.x;
    int tx = tid & 7;        // d-group
    int ty = tid >> 3;       // j-group, [0,16)

    for (int idx = tid; idx < TWO_D * DD; idx += PTHREADS) {
        int k = idx / DD, d = idx % DD;
        sW2T[d * HP + k] = W2[idx];
    }
    if (tid < TWO_D) sA[tid] = A[row * TWO_D + tid];
    if (tid < DD) sb2[tid] = B2[tid];
    __syncthreads();

    // Per-ty-group online softmax state (wj >= 0, so M=0 is a safe floor).
    float M = 0.0f;
    float acc[6];
    #pragma unroll
    for (int m = 0; m < 6; m++) acc[m] = 0.0f;
    float lsum = 0.0f;
    int numJ = i + 1;
    const float* Bbase = Bv + (b * NN) * TWO_D;

    unsigned long long biap[6];   // (bias, 0) packed
    #pragma unroll
    for (int m = 0; m < 6; m++) {
        F2U u; u.f = make_float2(sb2[tx + 8 * m], 0.0f);
        biap[m] = u.u;
    }

    for (int jbase = 0; jbase < numJ; jbase += PJT) {
        // Build H tile: H[j][k] = gelu(A_i[k] + B_{jbase+j}[k])
        for (int q = tid; q < PJT * (TWO_D / 4); q += PTHREADS) {
            int j = q / (TWO_D / 4);
            int kk = (q % (TWO_D / 4)) * 4;
            float4 bv = *(const float4*)(Bbase + (jbase + j) * TWO_D + kk);
            float4 hv;
            hv.x = gelu_exact(sA[kk + 0] + bv.x);
            hv.y = gelu_exact(sA[kk + 1] + bv.y);
            hv.z = gelu_exact(sA[kk + 2] + bv.z);
            hv.w = gelu_exact(sA[kk + 3] + bv.w);
            *(float4*)(sH + j * HP + kk) = hv;
        }
        __syncthreads();

        // P tile: thread tile 4j x 6d, packed dual-FMA along k
        unsigned long long pk[4][6];
        #pragma unroll
        for (int jj = 0; jj < 4; jj++)
            #pragma unroll
            for (int m = 0; m < 6; m++) pk[jj][m] = biap[m];

        #pragma unroll 4
        for (int k = 0; k < TWO_D; k += 4) {
            unsigned long long w01[6], w23[6];
            #pragma unroll
            for (int m = 0; m < 6; m++) {
                ulonglong2 wv = *(const ulonglong2*)(sW2T + (tx + 8 * m) * HP + k);
                w01[m] = wv.x; w23[m] = wv.y;
            }
            #pragma unroll
            for (int jj = 0; jj < 4; jj++) {
                ulonglong2 hv = *(const ulonglong2*)(sH + (ty + 16 * jj) * HP + k);
                #pragma unroll
                for (int m = 0; m < 6; m++) {
                    pk[jj][m] = fma2(hv.x, w01[m], pk[jj][m]);
                    pk[jj][m] = fma2(hv.y, w23[m], pk[jj][m]);
                }
            }
        }

        // Unpack (even+odd partials) -> p[jj][m]
        float p[4][6];
        #pragma unroll
        for (int jj = 0; jj < 4; jj++)
            #pragma unroll
            for (int m = 0; m < 6; m++) {
                F2U u; u.u = pk[jj][m];
                p[jj][m] = u.f.x + u.f.y;
            }

        // Pair-feature norms: reduce across the 8 tx lanes of this ty-group
        float wj[4];
        #pragma unroll
        for (int jj = 0; jj < 4; jj++) {
            float sq = 0.0f;
            #pragma unroll
            for (int m = 0; m < 6; m++) sq = fmaf(p[jj][m], p[jj][m], sq);
            sq += __shfl_xor_sync(0xFFFFFFFFu, sq, 1);
            sq += __shfl_xor_sync(0xFFFFFFFFu, sq, 2);
            sq += __shfl_xor_sync(0xFFFFFFFFu, sq, 4);
            int j = jbase + ty + 16 * jj;
            wj[jj] = (j <= i) ? sqrtf(sq) : -INFINITY;
        }

        // Per-group online softmax update
        float tmax = fmaxf(fmaxf(wj[0], wj[1]), fmaxf(wj[2], wj[3]));
        float newM = fmaxf(M, tmax);
        float sc = __expf(M - newM);
        #pragma unroll
        for (int m = 0; m < 6; m++) acc[m] *= sc;
        lsum *= sc;
        #pragma unroll
        for (int jj = 0; jj < 4; jj++) {
            float e = __expf(wj[jj] - newM);   // exactly 0 for masked j
            #pragma unroll
            for (int m = 0; m < 6; m++) acc[m] = fmaf(e, p[jj][m], acc[m]);
            lsum += e;
        }
        M = newM;
        __syncthreads();   // protect sH before next tile overwrites
    }

    #pragma unroll
    for (int m = 0; m < 6; m++) sacc[ty * DD + tx + 8 * m] = acc[m];
    if (tx == 0) { slsum[ty] = lsum; sM[ty] = M; }
    __syncthreads();

    if (tid < DD) {
        float Mstar = sM[0];
        #pragma unroll
        for (int w = 1; w < 16; w++) Mstar = fmaxf(Mstar, sM[w]);
        float a = 0.0f, L = 0.0f;
        #pragma unroll
        for (int w = 0; w < 16; w++) {
            float s = __expf(sM[w] - Mstar);
            a = fmaf(s, sacc[w * DD + tid], a);
            L = fmaf(s, slsum[w], L);
        }
        outp[row * DD + tid] = a / L;
    }
}

// ---------------------------------------------------------------------------
// Triple module: one row per block, 6-item batch, float4 LDS + 4-wide LDG.
// ---------------------------------------------------------------------------
__global__ __launch_bounds__(TWO_D) void triple_kernel(const float* __restrict__ x,
                              const int* __restrict__ ji,
                              const int* __restrict__ ki,
                              const float* __restrict__ W1,
                              const float* __restrict__ B1,
                              const float* __restrict__ W2,
                              const float* __restrict__ B2,
                              float* __restrict__ outt) {
    __shared__ __align__(16) float v[SS][THREE_D];
    __shared__ __align__(16) float hh[SS][TWO_D];
    __shared__ float sp2[2][DD];
    __shared__ int sidx[SS][2];
    int row = blockIdx.x;
    int b = row >> 8;
    int tid = threadIdx.x;     // 96

    if (tid < SS * 2) {
        int s = tid >> 1;
        sidx[s][tid & 1] = (tid & 1) ? ki[row * SS + s] : ji[row * SS + s];
    }
    __syncthreads();

    for (int q = tid; q < SS * 36; q += TWO_D) {
        int s = q / 36;
        int rem = q % 36;
        int seg = rem / 12;          // 0=xi, 1=xj, 2=xk
        int f4 = rem % 12;
        int srcrow = (seg == 0) ? row : (b * NN + sidx[s][seg - 1]);
        float4 val = *(const float4*)(x + srcrow * DD + f4 * 4);
        *(float4*)(&v[s][seg * DD + f4 * 4]) = val;
    }
    __syncthreads();

    {
        float h[SS];
        float bb = B1[tid];
        #pragma unroll
        for (int s = 0; s < SS; s++) h[s] = bb;
        const float* w1c = W1 + tid;
        #pragma unroll 3
        for (int k = 0; k < THREE_D; k += 4) {
            float w0 = w1c[(k + 0) * TWO_D];
            float w1 = w1c[(k + 1) * TWO_D];
            float w2 = w1c[(k + 2) * TWO_D];
            float w3 = w1c[(k + 3) * TWO_D];
            #pragma unroll
            for (int s = 0; s < SS; s++) {
                float4 vv = *(const float4*)(&v[s][k]);
                h[s] = fmaf(vv.x, w0, h[s]);
                h[s] = fmaf(vv.y, w1, h[s]);
                h[s] = fmaf(vv.z, w2, h[s]);
                h[s] = fmaf(vv.w, w3, h[s]);
            }
        }
        #pragma unroll
        for (int s = 0; s < SS; s++) hh[s][tid] = gelu_exact(h[s]);
    }
    __syncthreads();

    {
        int col = tid % DD;
        int g = tid / DD;            // 0 or 1
        float p[3];
        float bb = B2[col];
        #pragma unroll
        for (int q = 0; q < 3; q++) p[q] = bb;
        const float* w2c = W2 + col;
        #pragma unroll 3
        for (int k = 0; k < TWO_D; k += 4) {
            float w0 = w2c[(k + 0) * DD];
            float w1 = w2c[(k + 1) * DD];
            float w2 = w2c[(k + 2) * DD];
            float w3 = w2c[(k + 3) * DD];
            #pragma unroll
            for (int q = 0; q < 3; q++) {
                float4 hv = *(const float4*)(&hh[g * 3 + q][k]);
                p[q] = fmaf(hv.x, w0, p[q]);
                p[q] = fmaf(hv.y, w1, p[q]);
                p[q] = fmaf(hv.z, w2, p[q]);
                p[q] = fmaf(hv.w, w3, p[q]);
            }
        }
        sp2[g][col] = p[0] + p[1] + p[2];
    }
    __syncthreads();
    if (tid < DD)
        outt[row * DD + tid] = (sp2[0][tid] + sp2[1][tid]) * (1.0f / 6.0f);
}

// ---------------------------------------------------------------------------
// Fused gate/mix/LN1 + FFN/LN2. 192 threads / block.
// ---------------------------------------------------------------------------
__global__ __launch_bounds__(FOUR_D) void mixffn_kernel(float* __restrict__ x,
                              const float* __restrict__ p,
                              const float* __restrict__ t,
                              const float* __restrict__ Gw,
                              const float* __restrict__ Gb,
                              const float* __restrict__ n1g,
                              const float* __restrict__ n1b,
                              const float* __restrict__ W1,
                              const float* __restrict__ B1,
                              const float* __restrict__ W2,
                              const float* __restrict__ B2,
                              const float* __restrict__ n2g,
                              const float* __restrict__ n2b) {
    __shared__ float sp[DD], st[DD], sx[DD], sy[DD], sg[2 * DD], sh2[FOUR_D];
    int row = blockIdx.x;
    int tid = threadIdx.x;
    if (tid < DD) {
        sp[tid] = p[row * DD + tid];
        st[tid] = t[row * DD + tid];
        sx[tid] = x[row * DD + tid];
    }
    __syncthreads();
    if (tid < 2 * DD) {
        int d = tid % DD;
        int part = tid / DD;
        const float* src = part ? st : sp;
        const float* gw = Gw + part * DD * DD;
        float s = 0.0f;
        #pragma unroll 8
        for (int c = 0; c < DD; c++) s = fmaf(src[c], gw[c * DD + d], s);
        sg[tid] = s;
    }
    __syncthreads();
    if (tid < DD) {
        float gsum = sg[tid] + sg[DD + tid] + Gb[tid];
        float g = 1.0f / (1.0f + __expf(-gsum));
        sy[tid] = sx[tid] + g * sp[tid] + (1.0f - g) * st[tid];
    }
    __syncthreads();
    if (tid < DD) {
        float mu = 0.0f;
        #pragma unroll 8
        for (int c = 0; c < DD; c++) mu += sy[c];
        mu *= (1.0f / DD);
        float var = 0.0f;
        #pragma unroll 8
        for (int c = 0; c < DD; c++) { float d = sy[c] - mu; var = fmaf(d, d, var); }
        var *= (1.0f / DD);
        sp[tid] = (sy[tid] - mu) * rsqrtf(var + 1e-5f) * n1g[tid] + n1b[tid];
    }
    __syncthreads();
    {
        float h = B1[tid];
        #pragma unroll 8
        for (int c = 0; c < DD; c++) h = fmaf(sp[c], W1[c * FOUR_D + tid], h);
        sh2[tid] = gelu_exact(h);
    }
    __syncthreads();
    if (tid < DD) {
        float o = B2[tid];
        #pragma unroll 8
        for (int k = 0; k < FOUR_D; k++) o = fmaf(sh2[k], W2[k * DD + tid], o);
        sy[tid] = sp[tid] + o;
    }
    __syncthreads();
    if (tid < DD) {
        float mu = 0.0f;
        #pragma unroll 8
        for (int c = 0; c < DD; c++) mu += sy[c];
        mu *= (1.0f / DD);
        float var = 0.0f;
        #pragma unroll 8
        for (int c = 0; c < DD; c++) { float d = sy[c] - mu; var = fmaf(d, d, var); }
        var *= (1.0f / DD);
        x[row * DD + tid] = (sy[tid] - mu) * rsqrtf(var + 1e-5f) * n2g[tid] + n2b[tid];
    }
}

// ---------------------------------------------------------------------------
// Head
// ---------------------------------------------------------------------------
__global__ void head_kernel(const float* __restrict__ x,
                            const float* __restrict__ Hw,
                            const float* __restrict__ Hb,
                            float* __restrict__ out) {
    __shared__ float sx[DD];
    int row = blockIdx.x;
    int tid = threadIdx.x;
    sx[tid] = x[row * DD + tid];
    if (tid < 16) sx[tid + 32] = x[row * DD + tid + 32];
    __syncwarp();
    if (tid < VV) {
        float o = Hb[tid];
        #pragma unroll 8
        for (int d = 0; d < DD; d++) o = fmaf(sx[d], Hw[d * VV + tid], o);
        out[row * VV + tid] = o;
    }
}

// ---------------------------------------------------------------------------
// Launch (triple before pair so ncu's capture slot lands on pair_kernel)
// ---------------------------------------------------------------------------
extern "C" void kernel_launch(void* const* d_in, const int* in_sizes, int n_in,
                              void* d_out, int out_size) {
    const int*   ids     = (const int*)d_in[0];
    const int*   ji      = (const int*)d_in[1];
    const int*   ki      = (const int*)d_in[2];
    const float* embed   = (const float*)d_in[3];
    const float* pos     = (const float*)d_in[4];
    const float* pair_w1 = (const float*)d_in[5];
    const float* pair_b1 = (const float*)d_in[6];
    const float* pair_w2 = (const float*)d_in[7];
    const float* pair_b2 = (const float*)d_in[8];
    const float* tri_w1  = (const float*)d_in[9];
    const float* tri_b1  = (const float*)d_in[10];
    const float* tri_w2  = (const float*)d_in[11];
    const float* tri_b2  = (const float*)d_in[12];
    const float* gate_w  = (const float*)d_in[13];
    const float* gate_b  = (const float*)d_in[14];
    const float* n1_g    = (const float*)d_in[15];
    const float* n1_b    = (const float*)d_in[16];
    const float* ffn_w1  = (const float*)d_in[17];
    const float* ffn_b1  = (const float*)d_in[18];
    const float* ffn_w2  = (const float*)d_in[19];
    const float* ffn_b2  = (const float*)d_in[20];
    const float* n2_g    = (const float*)d_in[21];
    const float* n2_b    = (const float*)d_in[22];
    const float* head_w  = (const float*)d_in[23];
    const float* head_b  = (const float*)d_in[24];
    float* out = (float*)d_out;

    float* x; cudaGetSymbolAddress((void**)&x, g_x);
    float* p; cudaGetSymbolAddress((void**)&p, g_p);
    float* t; cudaGetSymbolAddress((void**)&t, g_t);
    float* Aa; cudaGetSymbolAddress((void**)&Aa, g_A);
    float* Bb; cudaGetSymbolAddress((void**)&Bb, g_B);

    embed_kernel<<<ROWS, DD>>>(ids, embed, pos, x);

    for (int l = 0; l < LL; l++) {
        ab_kernel<<<ROWS / 8, 192>>>(x, pair_w1 + l * TWO_D * TWO_D,
                                     pair_b1 + l * TWO_D, Aa, Bb);
        triple_kernel<<<ROWS, TWO_D>>>(
            x, ji + l * ROWS * SS, ki + l * ROWS * SS,
            tri_w1 + l * THREE_D * TWO_D, tri_b1 + l * TWO_D,
            tri_w2 + l * TWO_D * DD,      tri_b2 + l * DD, t);
        pair_kernel<<<ROWS, PTHREADS>>>(Aa, Bb,
            pair_w2 + l * TWO_D * DD, pair_b2 + l * DD, p);
        mixffn_kernel<<<ROWS, FOUR_D>>>(
            x, p, t,
            gate_w + l * TWO_D * DD, gate_b + l * DD,
            n1_g + l * DD, n1_b + l * DD,
            ffn_w1 + l * DD * FOUR_D, ffn_b1 + l * FOUR_D,
            ffn_w2 + l * FOUR_D * DD, ffn_b2 + l * DD,
            n2_g + l * DD, n2_b + l * DD);
    }

    head_kernel<<<ROWS, 32>>>(x, head_w, head_b, out);
}